// round 9
// baseline (speedup 1.0000x reference)
#include <cuda_runtime.h>
#include <cuda_fp16.h>
#include <cstdint>

// ===================== problem constants =====================
#define N_TOTAL   32000
#define M_TOTAL   1024
#define K_TOTAL   16384
#define K_CHUNKS  256            // K chunks of 64 fp16 (128 B per row fp16)
#define STAGES    4
#define STAGE_BYTES 49152        // A[128x64 f16]=16K + B[256x64 f16]=32K
#define GEMM_SMEM (STAGES * STAGE_BYTES)   // 192 KB
#define AROW_BYTES (K_TOTAL * 2)                   // X16 row
#define A_J_STRIDE ((size_t)32 * AROW_BYTES)       // 32 rows of X16
#define WROW_BYTES ((size_t)K_TOTAL * 4)           // W fp32 row
#define W_J_STRIDE ((size_t)32 * WROW_BYTES)       // 32 rows of W

// fp16 X scratch (device global: allocation-free rule workaround)
__device__ __align__(128) unsigned char g_X16[(size_t)M_TOTAL * K_TOTAL * 2]; // 32 MB

// ===================== helpers =====================
__device__ __forceinline__ uint32_t smem_u32(const void* p) {
    uint32_t a;
    asm("{ .reg .u64 t; cvta.to.shared.u64 t, %1; cvt.u32.u64 %0, t; }" : "=r"(a) : "l"(p));
    return a;
}

__device__ __forceinline__ void ldsm_x4(uint32_t& r0, uint32_t& r1, uint32_t& r2, uint32_t& r3,
                                        uint32_t addr) {
    asm volatile("ldmatrix.sync.aligned.m8n8.x4.shared.b16 {%0,%1,%2,%3}, [%4];"
                 : "=r"(r0), "=r"(r1), "=r"(r2), "=r"(r3) : "r"(addr));
}

__device__ __forceinline__ void mma16816(float& d0, float& d1, float& d2, float& d3,
                                         uint32_t a0, uint32_t a1, uint32_t a2, uint32_t a3,
                                         uint32_t b0, uint32_t b1) {
    asm volatile("mma.sync.aligned.m16n8k16.row.col.f32.f16.f16.f32 "
                 "{%0,%1,%2,%3}, {%4,%5,%6,%7}, {%8,%9}, {%0,%1,%2,%3};"
                 : "+f"(d0), "+f"(d1), "+f"(d2), "+f"(d3)
                 : "r"(a0), "r"(a1), "r"(a2), "r"(a3), "r"(b0), "r"(b1));
}

#define CP_ASYNC_16(dst, src) \
    asm volatile("cp.async.cg.shared.global [%0], [%1], 16;" :: "r"(dst), "l"(src) : "memory")
#define CP_COMMIT()  asm volatile("cp.async.commit_group;" ::: "memory")
#define CP_WAIT(n)   asm volatile("cp.async.wait_group %0;" :: "n"(n) : "memory")
#define STS128(addr, r0, r1, r2, r3) \
    asm volatile("st.shared.v4.b32 [%0], {%1,%2,%3,%4};" \
                 :: "r"(addr), "r"(r0), "r"(r1), "r"(r2), "r"(r3) : "memory")

__device__ __forceinline__ uint32_t pack_h2(float a, float b) {
    __half2 h = __floats2half2_rn(a, b);
    return *reinterpret_cast<uint32_t*>(&h);
}

// ===================== phase 1: gather selected layers -> X fp16 =====================
__global__ void slr_conv_x(const float* __restrict__ H) {
    const float4* src = reinterpret_cast<const float4*>(H);
    uint2* dst = reinterpret_cast<uint2*>(g_X16);
    const int total4 = M_TOTAL * K_TOTAL / 4;           // 4,194,304
    const int stride = gridDim.x * blockDim.x;
    for (int i = blockIdx.x * blockDim.x + threadIdx.x; i < total4; i += stride) {
        int m     = i >> 12;            // 4096 float4 per X row
        int k4    = i & 4095;
        int lsel  = k4 >> 10;
        int rest4 = k4 & 1023;
        int layer = (lsel < 3) ? lsel * 6 : 23;   // {0,6,12,23}
        int b = m >> 9, s = m & 511;
        size_t s4 = ((size_t)(layer * 2 + b) * 512 + s) * 1024 + rest4;
        float4 v = src[s4];
        uint2 o;
        o.x = pack_h2(v.x, v.y);
        o.y = pack_h2(v.z, v.w);
        dst[i] = o;
    }
}

// ===================== phase 2: fp16 mma.sync GEMM with fused W conversion ==========
// CTA 128(M) x 256(N), K-chunk 64. 8 warps 2(M) x 4(N): warp tile 64x64.
// A: cp.async from g_X16 (fp16). B: LDG fp32 from W -> cvt -> STS fp16 (one chunk ahead).
__global__ void __launch_bounds__(256, 1)
slr_gemm(const float* __restrict__ W, const float* __restrict__ bias,
         float* __restrict__ out) {
    extern __shared__ unsigned char smem_raw[];
    const uint32_t smem0 = smem_u32(smem_raw);

    const int tid  = threadIdx.x;
    const int wid  = tid >> 5;
    const int lane = tid & 31;

    const int m_tile = blockIdx.x & 7;          // 8 m-tiles consecutive: share W block in L2
    const int n_tile = blockIdx.x >> 3;
    const int m0 = m_tile * 128;
    const int n0 = n_tile * 256;

    // ---------- producer constants ----------
    const int rA  = tid >> 3;                   // 0..31
    const int c16 = tid & 7;                    // 16B-column within 128B fp16 row
    const uint32_t sw = (uint32_t)((c16 ^ (rA & 7)) << 4);
    const uint32_t dstA0 = (uint32_t)rA * 128u + sw;
    const uint32_t dstB0 = 16384u + (uint32_t)rA * 128u + sw;
    const unsigned char* srcA0 = g_X16 + (size_t)(m0 + rA) * AROW_BYTES + c16 * 16;
    // fp32 W: 16B fp16 dst needs 32B fp32 src at (row, chunk*256 + c16*32)
    const unsigned char* srcB0 = reinterpret_cast<const unsigned char*>(W)
                               + (size_t)(n0 + rA) * WROW_BYTES + c16 * 32;

    // ---------- ldmatrix address components ----------
    const int warp_m = wid & 1;
    const int warp_n = wid >> 1;
    const int sub    = lane >> 3;
    const int l7     = lane & 7;
    const int hiA    = sub >> 1;
    const int hiB    = sub & 1;

    uint32_t aRow128[4];  int aXor[4];
#pragma unroll
    for (int mt = 0; mt < 4; mt++) {
        int r = warp_m * 64 + mt * 16 + (sub & 1) * 8 + l7;
        aRow128[mt] = (uint32_t)r * 128u;
        aXor[mt]    = r & 7;
    }
    uint32_t bRow128[4];  int bXor[4];
#pragma unroll
    for (int g = 0; g < 4; g++) {
        int r = warp_n * 64 + g * 16 + (sub >> 1) * 8 + l7;
        bRow128[g] = (uint32_t)r * 128u;
        bXor[g]    = r & 7;
    }

    float acc[4][8][4];
#pragma unroll
    for (int i = 0; i < 4; i++)
#pragma unroll
        for (int j = 0; j < 8; j++)
#pragma unroll
            for (int q = 0; q < 4; q++) acc[i][j][q] = 0.0f;

    float4 braw[16];   // B fp32 for one chunk: 8 rows x 2 float4

    // ---------- prologue: B chunks 0..2 (LDG+cvt+STS), A chunks 0..2 (cp.async) ----------
#pragma unroll 1
    for (int p = 0; p < STAGES - 1; p++) {
        const uint32_t st = smem0 + (uint32_t)p * STAGE_BYTES;
        const size_t wof = (size_t)p * 256;
#pragma unroll
        for (int j = 0; j < 8; j++) {
            const float4* s = reinterpret_cast<const float4*>(srcB0 + j * W_J_STRIDE + wof);
            braw[2 * j]     = s[0];
            braw[2 * j + 1] = s[1];
        }
#pragma unroll
        for (int j = 0; j < 8; j++) {
            float4 v0 = braw[2 * j], v1 = braw[2 * j + 1];
            STS128(st + dstB0 + (uint32_t)j * 4096u,
                   pack_h2(v0.x, v0.y), pack_h2(v0.z, v0.w),
                   pack_h2(v1.x, v1.y), pack_h2(v1.z, v1.w));
        }
        const size_t aof = (size_t)p * 128;
#pragma unroll
        for (int j = 0; j < 4; j++)
            CP_ASYNC_16(st + dstA0 + (uint32_t)j * 4096u, srcA0 + j * A_J_STRIDE + aof);
        CP_COMMIT();
    }
    // preload B chunk 3 into regs
#pragma unroll
    for (int j = 0; j < 8; j++) {
        const float4* s = reinterpret_cast<const float4*>(srcB0 + j * W_J_STRIDE + (size_t)3 * 256);
        braw[2 * j]     = s[0];
        braw[2 * j + 1] = s[1];
    }

    // ---------- mainloop ----------
    for (int c = 0; c < K_CHUNKS; c++) {
        CP_WAIT(STAGES - 2);
        __syncthreads();

        const int cn = c + STAGES - 1;          // chunk entering the pipeline
        if (cn < K_CHUNKS) {
            const uint32_t st = smem0 + (uint32_t)(cn & (STAGES - 1)) * STAGE_BYTES;
            // store B chunk cn (regs loaded last iteration; data long since arrived)
#pragma unroll
            for (int j = 0; j < 8; j++) {
                float4 v0 = braw[2 * j], v1 = braw[2 * j + 1];
                STS128(st + dstB0 + (uint32_t)j * 4096u,
                       pack_h2(v0.x, v0.y), pack_h2(v0.z, v0.w),
                       pack_h2(v1.x, v1.y), pack_h2(v1.z, v1.w));
            }
            // start LDG for B chunk cn+1
            if (cn + 1 < K_CHUNKS) {
                const size_t wof = (size_t)(cn + 1) * 256;
#pragma unroll
                for (int j = 0; j < 8; j++) {
                    const float4* s = reinterpret_cast<const float4*>(srcB0 + j * W_J_STRIDE + wof);
                    braw[2 * j]     = s[0];
                    braw[2 * j + 1] = s[1];
                }
            }
            // A chunk cn via cp.async
            const size_t aof = (size_t)cn * 128;
#pragma unroll
            for (int j = 0; j < 4; j++)
                CP_ASYNC_16(st + dstA0 + (uint32_t)j * 4096u, srcA0 + j * A_J_STRIDE + aof);
        }
        CP_COMMIT();   // unconditional: keeps wait_group(N) semantics exact in the tail

        const uint32_t stA = smem0 + (uint32_t)(c & (STAGES - 1)) * STAGE_BYTES;
        const uint32_t stB = stA + 16384u;

#pragma unroll
        for (int s = 0; s < 4; s++) {
            uint32_t a[4][4];
#pragma unroll
            for (int mt = 0; mt < 4; mt++) {
                uint32_t addr = stA + aRow128[mt]
                              + (uint32_t)(((2 * s + hiA) ^ aXor[mt]) << 4);
                ldsm_x4(a[mt][0], a[mt][1], a[mt][2], a[mt][3], addr);
            }
            uint32_t b[8][2];
#pragma unroll
            for (int g = 0; g < 4; g++) {
                uint32_t addr = stB + bRow128[g]
                              + (uint32_t)(((2 * s + hiB) ^ bXor[g]) << 4);
                uint32_t r0, r1, r2, r3;
                ldsm_x4(r0, r1, r2, r3, addr);
                b[g * 2 + 0][0] = r0; b[g * 2 + 0][1] = r1;
                b[g * 2 + 1][0] = r2; b[g * 2 + 1][1] = r3;
            }
#pragma unroll
            for (int mt = 0; mt < 4; mt++)
#pragma unroll
                for (int nt = 0; nt < 8; nt++)
                    mma16816(acc[mt][nt][0], acc[mt][nt][1], acc[mt][nt][2], acc[mt][nt][3],
                             a[mt][0], a[mt][1], a[mt][2], a[mt][3],
                             b[nt][0], b[nt][1]);
        }
    }

    // ---------- epilogue ----------
    const int gid = lane >> 2;
    const int tig = lane & 3;
#pragma unroll
    for (int nt = 0; nt < 8; nt++) {
        const int col = n0 + warp_n * 64 + nt * 8 + 2 * tig;
        const float2 bv = *reinterpret_cast<const float2*>(bias + col);
#pragma unroll
        for (int mt = 0; mt < 4; mt++) {
            const int row = m0 + warp_m * 64 + mt * 16 + gid;
            float2 o0, o1;
            o0.x = acc[mt][nt][0] + bv.x;
            o0.y = acc[mt][nt][1] + bv.y;
            o1.x = acc[mt][nt][2] + bv.x;
            o1.y = acc[mt][nt][3] + bv.y;
            *reinterpret_cast<float2*>(out + (size_t)row * N_TOTAL + col) = o0;
            *reinterpret_cast<float2*>(out + (size_t)(row + 8) * N_TOTAL + col) = o1;
        }
    }
}

// ===================== launch =====================
extern "C" void kernel_launch(void* const* d_in, const int* in_sizes, int n_in,
                              void* d_out, int out_size) {
    const float* H = nullptr;   // all_hidden_states [24,2,512,512,8] = 100663296
    const float* W = nullptr;   // [32000,16384] = 524288000
    const float* B = nullptr;   // [32000]
    for (int i = 0; i < n_in; i++) {
        long long sz = in_sizes[i];
        if      (sz == 100663296LL) H = (const float*)d_in[i];
        else if (sz == 524288000LL) W = (const float*)d_in[i];
        else if (sz == 32000LL)     B = (const float*)d_in[i];
    }
    float* out = (float*)d_out;

    slr_conv_x<<<2048, 256>>>(H);

    cudaFuncSetAttribute(slr_gemm, cudaFuncAttributeMaxDynamicSharedMemorySize, GEMM_SMEM);
    slr_gemm<<<(M_TOTAL / 128) * (N_TOTAL / 256), 256, GEMM_SMEM>>>(W, B, out);
}

// round 10
// speedup vs baseline: 1.2258x; 1.2258x over previous
#include <cuda_runtime.h>
#include <cuda_fp16.h>
#include <cstdint>

// ===================== problem constants =====================
#define N_TOTAL   32000
#define M_TOTAL   1024
#define K_TOTAL   16384
#define K_CHUNKS  256            // K chunks of 64 fp16 (128 B per row)
#define STAGES    4
#define STAGE_BYTES 49152        // A[128x64 f16]=16K + B[256x64 f16]=32K
#define GEMM_SMEM (STAGES * STAGE_BYTES)   // 192 KB
#define ROW_BYTES (K_TOTAL * 2)
#define J_SRC_STRIDE ((size_t)32 * ROW_BYTES)   // 32 rows

// fp16 scratch (device globals: allocation-free rule workaround)
__device__ __align__(128) unsigned char g_W16[(size_t)N_TOTAL * K_TOTAL * 2]; // 1.05 GB
__device__ __align__(128) unsigned char g_X16[(size_t)M_TOTAL * K_TOTAL * 2]; // 32 MB

// ===================== helpers =====================
__device__ __forceinline__ uint32_t smem_u32(const void* p) {
    uint32_t a;
    asm("{ .reg .u64 t; cvta.to.shared.u64 t, %1; cvt.u32.u64 %0, t; }" : "=r"(a) : "l"(p));
    return a;
}

__device__ __forceinline__ void ldsm_x4(uint32_t& r0, uint32_t& r1, uint32_t& r2, uint32_t& r3,
                                        uint32_t addr) {
    asm volatile("ldmatrix.sync.aligned.m8n8.x4.shared.b16 {%0,%1,%2,%3}, [%4];"
                 : "=r"(r0), "=r"(r1), "=r"(r2), "=r"(r3) : "r"(addr));
}

__device__ __forceinline__ void mma16816(float& d0, float& d1, float& d2, float& d3,
                                         uint32_t a0, uint32_t a1, uint32_t a2, uint32_t a3,
                                         uint32_t b0, uint32_t b1) {
    asm volatile("mma.sync.aligned.m16n8k16.row.col.f32.f16.f16.f32 "
                 "{%0,%1,%2,%3}, {%4,%5,%6,%7}, {%8,%9}, {%0,%1,%2,%3};"
                 : "+f"(d0), "+f"(d1), "+f"(d2), "+f"(d3)
                 : "r"(a0), "r"(a1), "r"(a2), "r"(a3), "r"(b0), "r"(b1));
}

#define CP_ASYNC_16(dst, src) \
    asm volatile("cp.async.cg.shared.global [%0], [%1], 16;" :: "r"(dst), "l"(src) : "memory")
#define CP_COMMIT()  asm volatile("cp.async.commit_group;" ::: "memory")
#define CP_WAIT(n)   asm volatile("cp.async.wait_group %0;" :: "n"(n) : "memory")

// ===================== phase 1a: W fp32 -> fp16 =====================
__global__ void slr_conv_w(const float* __restrict__ W) {
    const float4* src = reinterpret_cast<const float4*>(W);
    uint2* dst = reinterpret_cast<uint2*>(g_W16);
    const size_t n4 = (size_t)N_TOTAL * K_TOTAL / 4;
    const size_t stride = (size_t)gridDim.x * blockDim.x;
    for (size_t i = (size_t)blockIdx.x * blockDim.x + threadIdx.x; i < n4; i += stride) {
        float4 v = src[i];
        __half2 a = __floats2half2_rn(v.x, v.y);
        __half2 b = __floats2half2_rn(v.z, v.w);
        uint2 o;
        o.x = *reinterpret_cast<uint32_t*>(&a);
        o.y = *reinterpret_cast<uint32_t*>(&b);
        dst[i] = o;
    }
}

// ===================== phase 1b: gather selected layers -> X fp16 =====================
__global__ void slr_conv_x(const float* __restrict__ H) {
    const float4* src = reinterpret_cast<const float4*>(H);
    uint2* dst = reinterpret_cast<uint2*>(g_X16);
    const int total4 = M_TOTAL * K_TOTAL / 4;           // 4,194,304
    const int stride = gridDim.x * blockDim.x;
    for (int i = blockIdx.x * blockDim.x + threadIdx.x; i < total4; i += stride) {
        int m     = i >> 12;            // 4096 float4 per X row
        int k4    = i & 4095;
        int lsel  = k4 >> 10;
        int rest4 = k4 & 1023;
        int layer = (lsel < 3) ? lsel * 6 : 23;   // {0,6,12,23}
        int b = m >> 9, s = m & 511;
        size_t s4 = ((size_t)(layer * 2 + b) * 512 + s) * 1024 + rest4;
        float4 v = src[s4];
        __half2 a = __floats2half2_rn(v.x, v.y);
        __half2 c = __floats2half2_rn(v.z, v.w);
        uint2 o;
        o.x = *reinterpret_cast<uint32_t*>(&a);
        o.y = *reinterpret_cast<uint32_t*>(&c);
        dst[i] = o;
    }
}

// ===================== phase 2: fp16 mma.sync GEMM =====================
// CTA 128(M) x 256(N), K-chunk 64. 8 warps in 2(M) x 4(N): warp tile 64x64.
// Register double-buffered ldmatrix fragments: s+1 loads overlap s MMAs.
__global__ void __launch_bounds__(256, 1)
slr_gemm(const float* __restrict__ bias, float* __restrict__ out) {
    extern __shared__ unsigned char smem_raw[];
    const uint32_t smem0 = smem_u32(smem_raw);

    const int tid  = threadIdx.x;
    const int wid  = tid >> 5;
    const int lane = tid & 31;

    const int m_tile = blockIdx.x & 7;          // 8 m-tiles consecutive: share W block in L2
    const int n_tile = blockIdx.x >> 3;
    const int m0 = m_tile * 128;
    const int n0 = n_tile * 256;

    // ---------- producer: 12 x 16B per thread per chunk (4 A + 8 B) ----------
    const int rA  = tid >> 3;
    const int c16 = tid & 7;
    const uint32_t sw = (uint32_t)((c16 ^ (rA & 7)) << 4);
    const uint32_t dstA0 = (uint32_t)rA * 128u + sw;
    const uint32_t dstB0 = 16384u + (uint32_t)rA * 128u + sw;
    const unsigned char* srcA0 = g_X16 + (size_t)(m0 + rA) * ROW_BYTES + c16 * 16;
    const unsigned char* srcB0 = g_W16 + (size_t)(n0 + rA) * ROW_BYTES + c16 * 16;

    // ---------- ldmatrix address components ----------
    const int warp_m = wid & 1;                 // 2 across M
    const int warp_n = wid >> 1;                // 4 across N
    const int sub    = lane >> 3;
    const int l7     = lane & 7;
    const int hiA    = sub >> 1;
    const int hiB    = sub & 1;

    uint32_t aRow128[4];  int aXor[4];
#pragma unroll
    for (int mt = 0; mt < 4; mt++) {
        int r = warp_m * 64 + mt * 16 + (sub & 1) * 8 + l7;
        aRow128[mt] = (uint32_t)r * 128u;
        aXor[mt]    = r & 7;
    }
    uint32_t bRow128[4];  int bXor[4];
#pragma unroll
    for (int g = 0; g < 4; g++) {
        int r = warp_n * 64 + g * 16 + (sub >> 1) * 8 + l7;
        bRow128[g] = (uint32_t)r * 128u;
        bXor[g]    = r & 7;
    }

    float acc[4][8][4];
#pragma unroll
    for (int i = 0; i < 4; i++)
#pragma unroll
        for (int j = 0; j < 8; j++)
#pragma unroll
            for (int q = 0; q < 4; q++) acc[i][j][q] = 0.0f;

    // double-buffered fragments
    uint32_t a[2][4][4];
    uint32_t b[2][8][2];

#define LOAD_FRAGS(buf, s) do {                                                   \
        _Pragma("unroll")                                                         \
        for (int mt = 0; mt < 4; mt++) {                                          \
            uint32_t addr = stA + aRow128[mt]                                     \
                          + (uint32_t)(((2 * (s) + hiA) ^ aXor[mt]) << 4);        \
            ldsm_x4(a[buf][mt][0], a[buf][mt][1], a[buf][mt][2], a[buf][mt][3],   \
                    addr);                                                        \
        }                                                                         \
        _Pragma("unroll")                                                         \
        for (int g = 0; g < 4; g++) {                                             \
            uint32_t addr = stB + bRow128[g]                                      \
                          + (uint32_t)(((2 * (s) + hiB) ^ bXor[g]) << 4);         \
            uint32_t r0, r1, r2, r3;                                              \
            ldsm_x4(r0, r1, r2, r3, addr);                                        \
            b[buf][g * 2 + 0][0] = r0; b[buf][g * 2 + 0][1] = r1;                 \
            b[buf][g * 2 + 1][0] = r2; b[buf][g * 2 + 1][1] = r3;                 \
        }                                                                         \
    } while (0)

    // ---------- prologue: fill STAGES-1 stages ----------
#pragma unroll
    for (int c = 0; c < STAGES - 1; c++) {
        uint32_t st = smem0 + (uint32_t)c * STAGE_BYTES;
        size_t cof = (size_t)c * 128;
#pragma unroll
        for (int j = 0; j < 4; j++)
            CP_ASYNC_16(st + dstA0 + (uint32_t)j * 4096u, srcA0 + j * J_SRC_STRIDE + cof);
#pragma unroll
        for (int j = 0; j < 8; j++)
            CP_ASYNC_16(st + dstB0 + (uint32_t)j * 4096u, srcB0 + j * J_SRC_STRIDE + cof);
        CP_COMMIT();
    }

    // ---------- mainloop ----------
    for (int c = 0; c < K_CHUNKS; c++) {
        CP_WAIT(STAGES - 2);
        __syncthreads();

        int cn = c + STAGES - 1;
        if (cn < K_CHUNKS) {
            uint32_t st = smem0 + (uint32_t)(cn & (STAGES - 1)) * STAGE_BYTES;
            size_t cof = (size_t)cn * 128;
#pragma unroll
            for (int j = 0; j < 4; j++)
                CP_ASYNC_16(st + dstA0 + (uint32_t)j * 4096u, srcA0 + j * J_SRC_STRIDE + cof);
#pragma unroll
            for (int j = 0; j < 8; j++)
                CP_ASYNC_16(st + dstB0 + (uint32_t)j * 4096u, srcB0 + j * J_SRC_STRIDE + cof);
        }
        CP_COMMIT();

        const uint32_t stA = smem0 + (uint32_t)(c & (STAGES - 1)) * STAGE_BYTES;
        const uint32_t stB = stA + 16384u;

        LOAD_FRAGS(0, 0);                       // prefetch s=0
#pragma unroll
        for (int s = 0; s < 4; s++) {
            const int cur = s & 1;
            if (s < 3) {
                const int nxt = (s + 1) & 1;
                switch (s) {                    // compile-time s for LOAD_FRAGS
                    case 0: LOAD_FRAGS(1, 1); break;
                    case 1: LOAD_FRAGS(0, 2); break;
                    default: LOAD_FRAGS(1, 3); break;
                }
                (void)nxt;
            }
#pragma unroll
            for (int mt = 0; mt < 4; mt++)
#pragma unroll
                for (int nt = 0; nt < 8; nt++)
                    mma16816(acc[mt][nt][0], acc[mt][nt][1], acc[mt][nt][2], acc[mt][nt][3],
                             a[cur][mt][0], a[cur][mt][1], a[cur][mt][2], a[cur][mt][3],
                             b[cur][nt][0], b[cur][nt][1]);
        }
    }

    // ---------- epilogue ----------
    const int gid = lane >> 2;       // row within m16
    const int tig = lane & 3;        // col pair within n8
#pragma unroll
    for (int nt = 0; nt < 8; nt++) {
        const int col = n0 + warp_n * 64 + nt * 8 + 2 * tig;
        const float2 bv = *reinterpret_cast<const float2*>(bias + col);
#pragma unroll
        for (int mt = 0; mt < 4; mt++) {
            const int row = m0 + warp_m * 64 + mt * 16 + gid;
            float2 o0, o1;
            o0.x = acc[mt][nt][0] + bv.x;
            o0.y = acc[mt][nt][1] + bv.y;
            o1.x = acc[mt][nt][2] + bv.x;
            o1.y = acc[mt][nt][3] + bv.y;
            *reinterpret_cast<float2*>(out + (size_t)row * N_TOTAL + col) = o0;
            *reinterpret_cast<float2*>(out + (size_t)(row + 8) * N_TOTAL + col) = o1;
        }
    }
#undef LOAD_FRAGS
}

// ===================== launch =====================
extern "C" void kernel_launch(void* const* d_in, const int* in_sizes, int n_in,
                              void* d_out, int out_size) {
    const float* H = nullptr;   // all_hidden_states [24,2,512,512,8] = 100663296
    const float* W = nullptr;   // [32000,16384] = 524288000
    const float* B = nullptr;   // [32000]
    for (int i = 0; i < n_in; i++) {
        long long sz = in_sizes[i];
        if      (sz == 100663296LL) H = (const float*)d_in[i];
        else if (sz == 524288000LL) W = (const float*)d_in[i];
        else if (sz == 32000LL)     B = (const float*)d_in[i];
    }
    float* out = (float*)d_out;

    slr_conv_w<<<2960, 256>>>(W);
    slr_conv_x<<<2048, 256>>>(H);

    cudaFuncSetAttribute(slr_gemm, cudaFuncAttributeMaxDynamicSharedMemorySize, GEMM_SMEM);
    slr_gemm<<<(M_TOTAL / 128) * (N_TOTAL / 256), 256, GEMM_SMEM>>>(B, out);
}